// round 3
// baseline (speedup 1.0000x reference)
#include <cuda_runtime.h>
#include <math.h>

// Problem constants
#define NROW 8192
#define DDIM 256
#define INV_T (1.0f / 0.07f)

// GEMM tiling
#define BM 128
#define BN 128
#define BK 32
#define TM 8
#define TN 8
#define NTHREADS 256
#define NSPLIT 4
#define CTILES (NROW / BN)            // 64 column tiles
#define CT_PER_BLK (CTILES / NSPLIT)  // 16 per block

// Scratch in device globals (no cudaMalloc allowed)
__device__ float g_fn[NROW * DDIM];   // normalized features, 8 MB
__device__ int   g_lab[NROW];
__device__ float g_S[NROW];           // sum exp (excl. diag)
__device__ float g_P[NROW];           // sum of positive logits
__device__ float g_C[NROW];           // positive count
__device__ int   g_lab_is32;          // 1 => labels buffer is int32, 0 => int64

// ---------------------------------------------------------------------------
// Kernel 0: detect label dtype. Under an int64 little-endian layout with
// values < 512 every odd int32 word is zero; under an int32 layout the odd
// words are random labels (all-zero has probability ~512^-4096). Reading the
// first 8192 int32 words is in-bounds under BOTH layouts.
// Single block => no cross-block ordering issues; writes an absolute value.
// ---------------------------------------------------------------------------
__global__ void detect_labdtype_kernel(const unsigned* __restrict__ lab32) {
    __shared__ int any;
    if (threadIdx.x == 0) any = 0;
    __syncthreads();
    int local = 0;
    for (int i = threadIdx.x; i < 4096; i += 256)
        local |= (lab32[2 * i + 1] != 0u);
    if (local) atomicOr(&any, 1);
    __syncthreads();
    if (threadIdx.x == 0) g_lab_is32 = any;
}

// ---------------------------------------------------------------------------
// Kernel 1: L2-normalize each row, load labels (either dtype), zero accums.
// One warp per row; D=256 -> 64 float4 per row -> 2 float4 per lane.
// ---------------------------------------------------------------------------
__global__ void prep_kernel(const float* __restrict__ f,
                            const void* __restrict__ lab) {
    int row  = blockIdx.x * 8 + (threadIdx.x >> 5);
    int lane = threadIdx.x & 31;
    if (row >= NROW) return;

    const float4* fr = reinterpret_cast<const float4*>(f + (size_t)row * DDIM);
    float4 v0 = fr[lane];
    float4 v1 = fr[lane + 32];

    float ss = v0.x * v0.x + v0.y * v0.y + v0.z * v0.z + v0.w * v0.w
             + v1.x * v1.x + v1.y * v1.y + v1.z * v1.z + v1.w * v1.w;
    #pragma unroll
    for (int o = 16; o > 0; o >>= 1) ss += __shfl_xor_sync(0xFFFFFFFFu, ss, o);

    float inv = 1.0f / fmaxf(sqrtf(ss), 1e-12f);
    v0.x *= inv; v0.y *= inv; v0.z *= inv; v0.w *= inv;
    v1.x *= inv; v1.y *= inv; v1.z *= inv; v1.w *= inv;

    float4* out = reinterpret_cast<float4*>(g_fn + (size_t)row * DDIM);
    out[lane]      = v0;
    out[lane + 32] = v1;

    if (lane == 0) {
        int lv;
        if (g_lab_is32) lv = reinterpret_cast<const int*>(lab)[row];
        else            lv = (int)reinterpret_cast<const long long*>(lab)[row];
        g_lab[row] = lv;
        g_S[row] = 0.0f;
        g_P[row] = 0.0f;
        g_C[row] = 0.0f;
    }
}

// ---------------------------------------------------------------------------
// Kernel 2: tiled fp32 GEMM (both operands K-major from g_fn) with fused
// epilogue: exp / self-mask / label-mask, accumulated per row, atomically
// merged into g_S/g_P/g_C at block end.
// Grid: (NSPLIT, NROW/BM). Block: 256 threads, each computes an 8x8 microtile.
// ---------------------------------------------------------------------------
__global__ __launch_bounds__(NTHREADS, 1)
void supcon_main_kernel() {
    __shared__ float As[BK][BM];   // [k][m]
    __shared__ float Bs[BK][BN];   // [k][n]
    __shared__ int   labB[BN];

    const int tid = threadIdx.x;
    const int tx  = tid & 15;      // 16 threads across N
    const int ty  = tid >> 4;      // 16 threads across M
    const int row0  = blockIdx.y * BM;
    const int rbase = row0 + ty * TM;
    const int cbase_local = tx * TN;

    int labI[TM];
    #pragma unroll
    for (int i = 0; i < TM; i++) labI[i] = g_lab[rbase + i];

    float accS[TM], accP[TM], accC[TM];
    #pragma unroll
    for (int i = 0; i < TM; i++) { accS[i] = 0.f; accP[i] = 0.f; accC[i] = 0.f; }

    const int ct0 = blockIdx.x * CT_PER_BLK;
    for (int ct = ct0; ct < ct0 + CT_PER_BLK; ct++) {
        const int col0 = ct * BN;

        if (tid < BN) labB[tid] = g_lab[col0 + tid];

        float acc[TM][TN];
        #pragma unroll
        for (int i = 0; i < TM; i++)
            #pragma unroll
            for (int j = 0; j < TN; j++) acc[i][j] = 0.f;

        for (int k0 = 0; k0 < DDIM; k0 += BK) {
            // Load 128x32 A and B tiles, transposed into [k][m] layout.
            // id -> (cg = id>>7 in 0..7, r = id&127): warp lanes hit
            // consecutive r -> all 32 banks -> conflict-free smem stores.
            #pragma unroll
            for (int q = 0; q < 4; q++) {
                int id = tid + NTHREADS * q;
                int r  = id & 127;
                int cg = id >> 7;
                float4 va = *reinterpret_cast<const float4*>(
                    &g_fn[(size_t)(row0 + r) * DDIM + k0 + cg * 4]);
                As[cg * 4 + 0][r] = va.x;
                As[cg * 4 + 1][r] = va.y;
                As[cg * 4 + 2][r] = va.z;
                As[cg * 4 + 3][r] = va.w;
                float4 vb = *reinterpret_cast<const float4*>(
                    &g_fn[(size_t)(col0 + r) * DDIM + k0 + cg * 4]);
                Bs[cg * 4 + 0][r] = vb.x;
                Bs[cg * 4 + 1][r] = vb.y;
                Bs[cg * 4 + 2][r] = vb.z;
                Bs[cg * 4 + 3][r] = vb.w;
            }
            __syncthreads();

            #pragma unroll
            for (int k = 0; k < BK; k++) {
                float a[TM], b[TN];
                *reinterpret_cast<float4*>(&a[0]) =
                    *reinterpret_cast<const float4*>(&As[k][ty * TM]);
                *reinterpret_cast<float4*>(&a[4]) =
                    *reinterpret_cast<const float4*>(&As[k][ty * TM + 4]);
                *reinterpret_cast<float4*>(&b[0]) =
                    *reinterpret_cast<const float4*>(&Bs[k][cbase_local]);
                *reinterpret_cast<float4*>(&b[4]) =
                    *reinterpret_cast<const float4*>(&Bs[k][cbase_local + 4]);
                #pragma unroll
                for (int i = 0; i < TM; i++)
                    #pragma unroll
                    for (int j = 0; j < TN; j++)
                        acc[i][j] += a[i] * b[j];
            }
            __syncthreads();
        }

        // Fused epilogue
        #pragma unroll
        for (int i = 0; i < TM; i++) {
            const int gi = rbase + i;
            #pragma unroll
            for (int j = 0; j < TN; j++) {
                const int gj = col0 + cbase_local + j;
                float l = acc[i][j] * INV_T;
                float e = __expf(l);
                if (gi != gj) {
                    accS[i] += e;
                    if (labI[i] == labB[cbase_local + j]) {
                        accP[i] += l;
                        accC[i] += 1.0f;
                    }
                }
            }
        }
        __syncthreads();  // labB reused next iteration
    }

    #pragma unroll
    for (int i = 0; i < TM; i++) {
        atomicAdd(&g_S[rbase + i], accS[i]);
        atomicAdd(&g_P[rbase + i], accP[i]);
        atomicAdd(&g_C[rbase + i], accC[i]);
    }
}

// ---------------------------------------------------------------------------
// Kernel 3: per-row term + global mean -> scalar loss.
// ---------------------------------------------------------------------------
__global__ void finalize_kernel(float* __restrict__ out) {
    __shared__ float red[256];
    int tid = threadIdx.x;
    float s = 0.0f;
    for (int i = tid; i < NROW; i += 256) {
        float c = g_C[i];
        float term = g_P[i] / fmaxf(c, 1.0f) - __logf(g_S[i] + 1e-6f);
        s += term;
    }
    red[tid] = s;
    __syncthreads();
    #pragma unroll
    for (int o = 128; o > 0; o >>= 1) {
        if (tid < o) red[tid] += red[tid + o];
        __syncthreads();
    }
    if (tid == 0) out[0] = -red[0] / (float)NROW;
}

// ---------------------------------------------------------------------------
extern "C" void kernel_launch(void* const* d_in, const int* in_sizes, int n_in,
                              void* d_out, int out_size) {
    const float* feats = (const float*)d_in[0];
    const void*  labs  = d_in[1];
    float*       out   = (float*)d_out;

    detect_labdtype_kernel<<<1, 256>>>((const unsigned*)labs);

    prep_kernel<<<NROW / 8, 256>>>(feats, labs);

    dim3 grid(NSPLIT, NROW / BM);
    supcon_main_kernel<<<grid, NTHREADS>>>();

    finalize_kernel<<<1, 256>>>(out);
}

// round 6
// speedup vs baseline: 11.7900x; 11.7900x over previous
#include <cuda_runtime.h>
#include <cuda_bf16.h>
#include <stdint.h>
#include <math.h>

// ---------------------------------------------------------------------------
// Problem constants
#define NROW 8192
#define DDIM 256
#define INV_T (1.0f / 0.07f)

// Tiling
#define BM 128
#define BN 128
#define NSPLIT 8
#define NTILES 8            // (NROW/BN)/NSPLIT column tiles per CTA
#define NTHREADS 256

// Shared memory layout (bytes). Row stride of a tile = 256 bf16 = 512 B.
#define SM_LAB 0            // 2 x 128 int labels (1024 B)
#define SM_A   1024         // 128 x 512B = 64 KB
#define SM_B0  (SM_A + 65536)
#define SM_B1  (SM_B0 + 65536)
#define SM_TOTAL (SM_B1 + 65536)   // 197632 B

// Device-global scratch (no cudaMalloc allowed)
__device__ __nv_bfloat16 g_fb[NROW * DDIM];   // normalized bf16 features, 4 MB
__device__ int   g_lab[NROW];
__device__ float g_S[NROW];
__device__ float g_P[NROW];
__device__ float g_C[NROW];
__device__ float g_sum;
__device__ int   g_lab_is32;

// ---------------------------------------------------------------------------
// PTX helpers (all sm_80-era: safe for plain sm_103 target)
// ---------------------------------------------------------------------------
__device__ __forceinline__ uint32_t smem_u32(const void* p) {
    uint32_t a;
    asm("{ .reg .u64 t; cvta.to.shared.u64 t, %1; cvt.u32.u64 %0, t; }"
        : "=r"(a) : "l"(p));
    return a;
}

__device__ __forceinline__ void ldsm_x4(uint32_t* r, uint32_t addr) {
    asm volatile("ldmatrix.sync.aligned.m8n8.x4.shared.b16 {%0,%1,%2,%3}, [%4];"
        : "=r"(r[0]), "=r"(r[1]), "=r"(r[2]), "=r"(r[3]) : "r"(addr));
}

__device__ __forceinline__ void mma_bf16(float* c, const uint32_t* a,
                                         uint32_t b0, uint32_t b1) {
    asm volatile("mma.sync.aligned.m16n8k16.row.col.f32.bf16.bf16.f32 "
        "{%0,%1,%2,%3},{%4,%5,%6,%7},{%8,%9},{%0,%1,%2,%3};"
        : "+f"(c[0]), "+f"(c[1]), "+f"(c[2]), "+f"(c[3])
        : "r"(a[0]), "r"(a[1]), "r"(a[2]), "r"(a[3]), "r"(b0), "r"(b1));
}

__device__ __forceinline__ void cp16(uint32_t dst, const void* src) {
    asm volatile("cp.async.cg.shared.global [%0], [%1], 16;"
                 :: "r"(dst), "l"(src) : "memory");
}
#define CP_COMMIT() asm volatile("cp.async.commit_group;" ::: "memory")
#define CP_WAIT0()  asm volatile("cp.async.wait_group 0;" ::: "memory")

// ---------------------------------------------------------------------------
// Kernel 0: label dtype detection (+ zero the final accumulator).
// int64 labels < 512 => every odd int32 word is zero; int32 labels => odd
// words are random labels. Reading 8192 int32 words is in-bounds either way.
// ---------------------------------------------------------------------------
__global__ void detect_labdtype_kernel(const unsigned* __restrict__ lab32) {
    __shared__ int any;
    if (threadIdx.x == 0) any = 0;
    __syncthreads();
    int local = 0;
    for (int i = threadIdx.x; i < 4096; i += 256)
        local |= (lab32[2 * i + 1] != 0u);
    if (local) atomicOr(&any, 1);
    __syncthreads();
    if (threadIdx.x == 0) { g_lab_is32 = any; g_sum = 0.0f; }
}

// ---------------------------------------------------------------------------
// Kernel 1: L2-normalize rows -> bf16, load labels, zero accumulators.
// One warp per row.
// ---------------------------------------------------------------------------
__global__ void prep_kernel(const float* __restrict__ f,
                            const void* __restrict__ lab) {
    int row  = blockIdx.x * 8 + (threadIdx.x >> 5);
    int lane = threadIdx.x & 31;
    if (row >= NROW) return;

    const float4* fr = reinterpret_cast<const float4*>(f + (size_t)row * DDIM);
    float4 v0 = fr[lane];
    float4 v1 = fr[lane + 32];

    float ss = v0.x*v0.x + v0.y*v0.y + v0.z*v0.z + v0.w*v0.w
             + v1.x*v1.x + v1.y*v1.y + v1.z*v1.z + v1.w*v1.w;
    #pragma unroll
    for (int o = 16; o > 0; o >>= 1) ss += __shfl_xor_sync(0xFFFFFFFFu, ss, o);

    float inv = 1.0f / fmaxf(sqrtf(ss), 1e-12f);

    __nv_bfloat162 p0 = __floats2bfloat162_rn(v0.x * inv, v0.y * inv);
    __nv_bfloat162 p1 = __floats2bfloat162_rn(v0.z * inv, v0.w * inv);
    __nv_bfloat162 p2 = __floats2bfloat162_rn(v1.x * inv, v1.y * inv);
    __nv_bfloat162 p3 = __floats2bfloat162_rn(v1.z * inv, v1.w * inv);

    uint2 w0, w1;
    w0.x = *reinterpret_cast<uint32_t*>(&p0);
    w0.y = *reinterpret_cast<uint32_t*>(&p1);
    w1.x = *reinterpret_cast<uint32_t*>(&p2);
    w1.y = *reinterpret_cast<uint32_t*>(&p3);
    *reinterpret_cast<uint2*>(&g_fb[(size_t)row * DDIM + lane * 4])       = w0;
    *reinterpret_cast<uint2*>(&g_fb[(size_t)row * DDIM + 128 + lane * 4]) = w1;

    if (lane == 0) {
        int lv;
        if (g_lab_is32) lv = reinterpret_cast<const int*>(lab)[row];
        else            lv = (int)reinterpret_cast<const long long*>(lab)[row];
        g_lab[row] = lv;
        g_S[row] = 0.0f; g_P[row] = 0.0f; g_C[row] = 0.0f;
    }
}

// ---------------------------------------------------------------------------
// Issue cp.async for a 128x256-bf16 tile (64 KB) into swizzled SMEM.
// Swizzle: 16B chunk index c within a 512B row stored at (c ^ (row & 7)).
// ---------------------------------------------------------------------------
__device__ __forceinline__ void load_tile_async(uint32_t smemBase,
                                                const char* gsrc) {
    const int tid = threadIdx.x;
    #pragma unroll
    for (int q = 0; q < 16; q++) {
        int idx = q * NTHREADS + tid;   // 0..4095
        int row = idx >> 5;
        int c   = idx & 31;
        uint32_t dst = smemBase + row * 512 + ((c ^ (row & 7)) << 4);
        cp16(dst, gsrc + row * 512 + c * 16);
    }
}

// ---------------------------------------------------------------------------
// Kernel 2: bf16 mma.sync GEMM + fused SupCon epilogue.
// Grid (NSPLIT, NROW/BM), 256 threads (8 warps; warp grid 4 M x 2 N).
// ---------------------------------------------------------------------------
__global__ __launch_bounds__(NTHREADS, 1)
void supcon_mma_kernel() {
    extern __shared__ char smem[];
    const uint32_t sbase = smem_u32(smem);
    int* labSm = reinterpret_cast<int*>(smem + SM_LAB);

    const int tid    = threadIdx.x;
    const int lane   = tid & 31;
    const int wid    = tid >> 5;
    const int warp_m = wid & 3;
    const int warp_n = wid >> 2;
    const int row0   = blockIdx.y * BM;
    const int ct0    = blockIdx.x * NTILES;

    const int laneM = lane & 15;
    const int laneC = lane >> 4;
    const int rq    = lane >> 2;
    const int cq    = lane & 3;

    // Rows owned by this thread: idx = mi*2 + s  ->  row.
    int gRow[4];
    #pragma unroll
    for (int mi = 0; mi < 2; mi++)
        #pragma unroll
        for (int s = 0; s < 2; s++)
            gRow[mi * 2 + s] = row0 + warp_m * 32 + mi * 16 + s * 8 + rq;

    int labI[4];
    #pragma unroll
    for (int i = 0; i < 4; i++) labI[i] = g_lab[gRow[i]];

    float accS[4] = {0.f, 0.f, 0.f, 0.f};
    float accP[4] = {0.f, 0.f, 0.f, 0.f};
    float accC[4] = {0.f, 0.f, 0.f, 0.f};

    const char* gfb = reinterpret_cast<const char*>(g_fb);

    // Prologue: A tile (reused for all column tiles) + B[0] + labels[0].
    load_tile_async(sbase + SM_A,  gfb + (size_t)row0 * 512);
    load_tile_async(sbase + SM_B0, gfb + (size_t)(ct0 * BN) * 512);
    if (tid < BN) labSm[tid] = g_lab[ct0 * BN + tid];
    CP_COMMIT();
    CP_WAIT0();
    __syncthreads();

    const uint32_t aTile = sbase + SM_A;

    for (int t = 0; t < NTILES; t++) {
        const int b = t & 1;
        const uint32_t bTile = sbase + (b ? SM_B1 : SM_B0);

        // Prefetch next B tile + labels into the other buffer (overlaps MMA).
        if (t + 1 < NTILES) {
            int col1 = (ct0 + t + 1) * BN;
            load_tile_async(sbase + (b ? SM_B0 : SM_B1),
                            gfb + (size_t)col1 * 512);
            if (tid < BN) labSm[(b ^ 1) * 128 + tid] = g_lab[col1 + tid];
            CP_COMMIT();
        }

        // ---- MMA: 128x128 tile, K=256 ----
        float c[2][8][4];
        #pragma unroll
        for (int mi = 0; mi < 2; mi++)
            #pragma unroll
            for (int nj = 0; nj < 8; nj++)
                #pragma unroll
                for (int e = 0; e < 4; e++) c[mi][nj][e] = 0.f;

        #pragma unroll
        for (int ks = 0; ks < 16; ks++) {
            uint32_t a0[4], a1[4];
            {
                int r  = warp_m * 32 + laneM;
                int ch = ks * 2 + laneC;
                ldsm_x4(a0, aTile + r * 512 + ((ch ^ (r & 7)) << 4));
                int r2 = r + 16;
                ldsm_x4(a1, aTile + r2 * 512 + ((ch ^ (r2 & 7)) << 4));
            }
            #pragma unroll
            for (int ng = 0; ng < 4; ng++) {
                uint32_t bf[4];
                int nr = warp_n * 64 + ng * 16 + laneM;
                int ch = ks * 2 + laneC;
                ldsm_x4(bf, bTile + nr * 512 + ((ch ^ (nr & 7)) << 4));
                mma_bf16(c[0][ng * 2],     a0, bf[0], bf[2]);
                mma_bf16(c[0][ng * 2 + 1], a0, bf[1], bf[3]);
                mma_bf16(c[1][ng * 2],     a1, bf[0], bf[2]);
                mma_bf16(c[1][ng * 2 + 1], a1, bf[1], bf[3]);
            }
        }

        // ---- Fused epilogue for this tile ----
        {
            const int col0 = (ct0 + t) * BN;
            const int* labT = labSm + b * 128;
            #pragma unroll
            for (int nj = 0; nj < 8; nj++) {
                const int nb = warp_n * 64 + nj * 8 + cq * 2;
                const int l0 = labT[nb];
                const int l1 = labT[nb + 1];
                const int gj0 = col0 + nb;
                #pragma unroll
                for (int mi = 0; mi < 2; mi++) {
                    #pragma unroll
                    for (int s = 0; s < 2; s++) {
                        const int idx = mi * 2 + s;
                        const int gi  = gRow[idx];
                        float v0 = c[mi][nj][s * 2 + 0] * INV_T;
                        float v1 = c[mi][nj][s * 2 + 1] * INV_T;
                        float e0 = __expf(v0);
                        float e1 = __expf(v1);
                        if (gi != gj0) {
                            accS[idx] += e0;
                            if (labI[idx] == l0) { accP[idx] += v0; accC[idx] += 1.f; }
                        }
                        if (gi != gj0 + 1) {
                            accS[idx] += e1;
                            if (labI[idx] == l1) { accP[idx] += v1; accC[idx] += 1.f; }
                        }
                    }
                }
            }
        }

        if (t + 1 < NTILES) CP_WAIT0();
        __syncthreads();
    }

    // Quad reduction (lanes cq=0..3 share the same rows), then atomics.
    #pragma unroll
    for (int i = 0; i < 4; i++) {
        accS[i] += __shfl_xor_sync(0xFFFFFFFFu, accS[i], 1);
        accS[i] += __shfl_xor_sync(0xFFFFFFFFu, accS[i], 2);
        accP[i] += __shfl_xor_sync(0xFFFFFFFFu, accP[i], 1);
        accP[i] += __shfl_xor_sync(0xFFFFFFFFu, accP[i], 2);
        accC[i] += __shfl_xor_sync(0xFFFFFFFFu, accC[i], 1);
        accC[i] += __shfl_xor_sync(0xFFFFFFFFu, accC[i], 2);
    }
    if (cq == 0) {
        #pragma unroll
        for (int i = 0; i < 4; i++) {
            atomicAdd(&g_S[gRow[i]], accS[i]);
            atomicAdd(&g_P[gRow[i]], accP[i]);
            atomicAdd(&g_C[gRow[i]], accC[i]);
        }
    }
}

// ---------------------------------------------------------------------------
// Kernel 3a: per-row term, block-reduce, atomic into g_sum (32 blocks).
// Kernel 3b: write scalar.
// ---------------------------------------------------------------------------
__global__ void finalize_partial_kernel() {
    int i = blockIdx.x * 256 + threadIdx.x;
    float c = g_C[i];
    float term = g_P[i] / fmaxf(c, 1.0f) - __logf(g_S[i] + 1e-6f);
    #pragma unroll
    for (int o = 16; o > 0; o >>= 1) term += __shfl_xor_sync(0xFFFFFFFFu, term, o);
    __shared__ float ws[8];
    if ((threadIdx.x & 31) == 0) ws[threadIdx.x >> 5] = term;
    __syncthreads();
    if (threadIdx.x == 0) {
        float s = 0.f;
        #pragma unroll
        for (int w = 0; w < 8; w++) s += ws[w];
        atomicAdd(&g_sum, s);
    }
}

__global__ void finalize_write_kernel(float* __restrict__ out) {
    out[0] = -g_sum / (float)NROW;
}

// ---------------------------------------------------------------------------
extern "C" void kernel_launch(void* const* d_in, const int* in_sizes, int n_in,
                              void* d_out, int out_size) {
    const float* feats = (const float*)d_in[0];
    const void*  labs  = d_in[1];
    float*       out   = (float*)d_out;

    cudaFuncSetAttribute(supcon_mma_kernel,
                         cudaFuncAttributeMaxDynamicSharedMemorySize, SM_TOTAL);

    detect_labdtype_kernel<<<1, 256>>>((const unsigned*)labs);
    prep_kernel<<<NROW / 8, 256>>>(feats, labs);

    dim3 grid(NSPLIT, NROW / BM);
    supcon_mma_kernel<<<grid, NTHREADS, SM_TOTAL>>>();

    finalize_partial_kernel<<<NROW / 256, 256>>>();
    finalize_write_kernel<<<1, 1>>>(out);
}

// round 7
// speedup vs baseline: 18.5622x; 1.5744x over previous
#include <cuda_runtime.h>
#include <cuda_bf16.h>
#include <stdint.h>
#include <math.h>

// ---------------------------------------------------------------------------
// Problem constants
#define NROW 8192
#define DDIM 256
// Features are pre-scaled by sqrt(1/TEMP) so the MMA emits logits directly.
#define SQRT_INV_T 3.77964473f

#define BM 128
#define NB (NROW / BM)                 // 64 row/col blocks
#define NPAIRS (NB * (NB + 1) / 2)     // 2080 tile pairs (bi <= bj)
#define NTHREADS 256

// Shared memory layout (bytes). Tile row stride = 256 bf16 = 512 B.
#define SM_LABA 0                      // 128 ints
#define SM_LABB 512                    // 128 ints
#define SM_A    1024                   // 64 KB
#define SM_B    (SM_A + 65536)
#define SM_TOTAL (SM_B + 65536)        // 132096 B

// Device-global scratch (no cudaMalloc allowed)
__device__ __nv_bfloat16 g_fb[NROW * DDIM];   // normalized*scaled bf16, 4 MB
__device__ int   g_lab[NROW];
__device__ float g_S[NROW];
__device__ float g_P[NROW];
__device__ float g_C[NROW];
__device__ float g_sum;
__device__ int   g_lab_is32;

// ---------------------------------------------------------------------------
// PTX helpers (sm_80-era only: safe for the plain sm_103 ptx target)
// ---------------------------------------------------------------------------
__device__ __forceinline__ uint32_t smem_u32(const void* p) {
    uint32_t a;
    asm("{ .reg .u64 t; cvta.to.shared.u64 t, %1; cvt.u32.u64 %0, t; }"
        : "=r"(a) : "l"(p));
    return a;
}

__device__ __forceinline__ void ldsm_x4(uint32_t* r, uint32_t addr) {
    asm volatile("ldmatrix.sync.aligned.m8n8.x4.shared.b16 {%0,%1,%2,%3}, [%4];"
        : "=r"(r[0]), "=r"(r[1]), "=r"(r[2]), "=r"(r[3]) : "r"(addr));
}

__device__ __forceinline__ void mma_bf16(float* c, const uint32_t* a,
                                         uint32_t b0, uint32_t b1) {
    asm volatile("mma.sync.aligned.m16n8k16.row.col.f32.bf16.bf16.f32 "
        "{%0,%1,%2,%3},{%4,%5,%6,%7},{%8,%9},{%0,%1,%2,%3};"
        : "+f"(c[0]), "+f"(c[1]), "+f"(c[2]), "+f"(c[3])
        : "r"(a[0]), "r"(a[1]), "r"(a[2]), "r"(a[3]), "r"(b0), "r"(b1));
}

__device__ __forceinline__ void cp16(uint32_t dst, const void* src) {
    asm volatile("cp.async.cg.shared.global [%0], [%1], 16;"
                 :: "r"(dst), "l"(src) : "memory");
}
#define CP_COMMIT() asm volatile("cp.async.commit_group;" ::: "memory")
#define CP_WAIT0()  asm volatile("cp.async.wait_group 0;" ::: "memory")

// ---------------------------------------------------------------------------
// Kernel 0: label dtype detection (+ zero the final accumulator).
// ---------------------------------------------------------------------------
__global__ void detect_labdtype_kernel(const unsigned* __restrict__ lab32) {
    __shared__ int any;
    if (threadIdx.x == 0) any = 0;
    __syncthreads();
    int local = 0;
    for (int i = threadIdx.x; i < 4096; i += 256)
        local |= (lab32[2 * i + 1] != 0u);
    if (local) atomicOr(&any, 1);
    __syncthreads();
    if (threadIdx.x == 0) { g_lab_is32 = any; g_sum = 0.0f; }
}

// ---------------------------------------------------------------------------
// Kernel 1: L2-normalize rows, scale by sqrt(1/T), cast bf16; labels; zeros.
// ---------------------------------------------------------------------------
__global__ void prep_kernel(const float* __restrict__ f,
                            const void* __restrict__ lab) {
    int row  = blockIdx.x * 8 + (threadIdx.x >> 5);
    int lane = threadIdx.x & 31;
    if (row >= NROW) return;

    const float4* fr = reinterpret_cast<const float4*>(f + (size_t)row * DDIM);
    float4 v0 = fr[lane];
    float4 v1 = fr[lane + 32];

    float ss = v0.x*v0.x + v0.y*v0.y + v0.z*v0.z + v0.w*v0.w
             + v1.x*v1.x + v1.y*v1.y + v1.z*v1.z + v1.w*v1.w;
    #pragma unroll
    for (int o = 16; o > 0; o >>= 1) ss += __shfl_xor_sync(0xFFFFFFFFu, ss, o);

    float inv = SQRT_INV_T / fmaxf(sqrtf(ss), 1e-12f);

    __nv_bfloat162 p0 = __floats2bfloat162_rn(v0.x * inv, v0.y * inv);
    __nv_bfloat162 p1 = __floats2bfloat162_rn(v0.z * inv, v0.w * inv);
    __nv_bfloat162 p2 = __floats2bfloat162_rn(v1.x * inv, v1.y * inv);
    __nv_bfloat162 p3 = __floats2bfloat162_rn(v1.z * inv, v1.w * inv);

    uint2 w0, w1;
    w0.x = *reinterpret_cast<uint32_t*>(&p0);
    w0.y = *reinterpret_cast<uint32_t*>(&p1);
    w1.x = *reinterpret_cast<uint32_t*>(&p2);
    w1.y = *reinterpret_cast<uint32_t*>(&p3);
    *reinterpret_cast<uint2*>(&g_fb[(size_t)row * DDIM + lane * 4])       = w0;
    *reinterpret_cast<uint2*>(&g_fb[(size_t)row * DDIM + 128 + lane * 4]) = w1;

    if (lane == 0) {
        int lv;
        if (g_lab_is32) lv = reinterpret_cast<const int*>(lab)[row];
        else            lv = (int)reinterpret_cast<const long long*>(lab)[row];
        g_lab[row] = lv;
        g_S[row] = 0.0f; g_P[row] = 0.0f; g_C[row] = 0.0f;
    }
}

// ---------------------------------------------------------------------------
// cp.async a 128x256-bf16 tile (64 KB) into swizzled SMEM.
// 16B chunk c within a 512B row stored at (c ^ (row & 7)).
// ---------------------------------------------------------------------------
__device__ __forceinline__ void load_tile_async(uint32_t smemBase,
                                                const char* gsrc) {
    const int tid = threadIdx.x;
    #pragma unroll
    for (int q = 0; q < 16; q++) {
        int idx = q * NTHREADS + tid;
        int row = idx >> 5;
        int c   = idx & 31;
        uint32_t dst = smemBase + row * 512 + ((c ^ (row & 7)) << 4);
        cp16(dst, gsrc + row * 512 + c * 16);
    }
}

// ---------------------------------------------------------------------------
// Kernel 2: symmetric bf16 mma.sync GEMM + fused SupCon epilogue.
// Grid: NPAIRS CTAs, one 128x128 tile pair (bi<=bj) each.
// Off-diagonal tiles feed BOTH the row block (bi) and, via column partials,
// the transposed row block (bj). Diagonal tiles: row side only, self-masked.
// ---------------------------------------------------------------------------
__global__ __launch_bounds__(NTHREADS, 1)
void supcon_sym_kernel() {
    extern __shared__ char smem[];
    const uint32_t sbase = smem_u32(smem);
    int* labA = reinterpret_cast<int*>(smem + SM_LABA);
    int* labB = reinterpret_cast<int*>(smem + SM_LABB);

    // Decode blockIdx.x -> (bi, bj), bi <= bj.  off(b) = b*NB - b*(b-1)/2.
    const int idx = blockIdx.x;
    int bi = (int)floorf((2.0f * NB + 1.0f
              - sqrtf((2.0f * NB + 1.0f) * (2.0f * NB + 1.0f) - 8.0f * idx)) * 0.5f);
    if (bi < 0) bi = 0;
    if (bi > NB - 1) bi = NB - 1;
    while (bi * NB - (bi * (bi - 1) >> 1) > idx) bi--;
    while ((bi + 1) * NB - ((bi + 1) * bi >> 1) <= idx) bi++;
    const int bj = bi + (idx - (bi * NB - (bi * (bi - 1) >> 1)));
    const bool diag = (bi == bj);

    const int row0 = bi * BM;
    const int col0 = bj * BM;

    const int tid    = threadIdx.x;
    const int lane   = tid & 31;
    const int wid    = tid >> 5;
    const int warp_m = wid & 3;
    const int warp_n = wid >> 2;
    const int laneM  = lane & 15;
    const int laneC  = lane >> 4;
    const int rq     = lane >> 2;
    const int cq     = lane & 3;

    int gRow[4];
    #pragma unroll
    for (int mi = 0; mi < 2; mi++)
        #pragma unroll
        for (int s = 0; s < 2; s++)
            gRow[mi * 2 + s] = row0 + warp_m * 32 + mi * 16 + s * 8 + rq;

    const char* gfb = reinterpret_cast<const char*>(g_fb);

    // Loads: A always; B only off-diagonal (diag reuses A).
    load_tile_async(sbase + SM_A, gfb + (size_t)row0 * 512);
    if (!diag) load_tile_async(sbase + SM_B, gfb + (size_t)col0 * 512);
    if (tid < BM)            labA[tid]       = g_lab[row0 + tid];
    else                     labB[tid - BM]  = g_lab[col0 + tid - BM];
    CP_COMMIT();

    int labI[4];
    #pragma unroll
    for (int i = 0; i < 4; i++) labI[i] = g_lab[gRow[i]];

    CP_WAIT0();
    __syncthreads();

    const uint32_t aTile = sbase + SM_A;
    const uint32_t bTile = diag ? aTile : (sbase + SM_B);
    const int* labT = diag ? labA : labB;

    // ---- MMA: 128x128 tile, K=256 ----
    float c[2][8][4];
    #pragma unroll
    for (int mi = 0; mi < 2; mi++)
        #pragma unroll
        for (int nj = 0; nj < 8; nj++)
            #pragma unroll
            for (int e = 0; e < 4; e++) c[mi][nj][e] = 0.f;

    #pragma unroll
    for (int ks = 0; ks < 16; ks++) {
        uint32_t a0[4], a1[4];
        {
            int r  = warp_m * 32 + laneM;
            int ch = ks * 2 + laneC;
            ldsm_x4(a0, aTile + r * 512 + ((ch ^ (r & 7)) << 4));
            int r2 = r + 16;
            ldsm_x4(a1, aTile + r2 * 512 + ((ch ^ (r2 & 7)) << 4));
        }
        #pragma unroll
        for (int ng = 0; ng < 4; ng++) {
            uint32_t bf[4];
            int nr = warp_n * 64 + ng * 16 + laneM;
            int ch = ks * 2 + laneC;
            ldsm_x4(bf, bTile + nr * 512 + ((ch ^ (nr & 7)) << 4));
            mma_bf16(c[0][ng * 2],     a0, bf[0], bf[2]);
            mma_bf16(c[0][ng * 2 + 1], a0, bf[1], bf[3]);
            mma_bf16(c[1][ng * 2],     a1, bf[0], bf[2]);
            mma_bf16(c[1][ng * 2 + 1], a1, bf[1], bf[3]);
        }
    }

    float accS[4] = {0.f, 0.f, 0.f, 0.f};
    float accP[4] = {0.f, 0.f, 0.f, 0.f};
    float accC[4] = {0.f, 0.f, 0.f, 0.f};

    if (diag) {
        // Row-side only, self-masked.
        #pragma unroll
        for (int nj = 0; nj < 8; nj++) {
            const int nb = warp_n * 64 + nj * 8 + cq * 2;
            const int l0 = labT[nb];
            const int l1 = labT[nb + 1];
            const int gj0 = col0 + nb;
            #pragma unroll
            for (int mi = 0; mi < 2; mi++) {
                #pragma unroll
                for (int s = 0; s < 2; s++) {
                    const int i4 = mi * 2 + s;
                    const int gi = gRow[i4];
                    float v0 = c[mi][nj][s * 2 + 0];
                    float v1 = c[mi][nj][s * 2 + 1];
                    float e0 = __expf(v0);
                    float e1 = __expf(v1);
                    if (gi != gj0) {
                        accS[i4] += e0;
                        if (labI[i4] == l0) { accP[i4] += v0; accC[i4] += 1.f; }
                    }
                    if (gi != gj0 + 1) {
                        accS[i4] += e1;
                        if (labI[i4] == l1) { accP[i4] += v1; accC[i4] += 1.f; }
                    }
                }
            }
        }
    } else {
        // Row side + column side (transposed contribution).
        float colS[16], colP[16], colC[16];
        #pragma unroll
        for (int i = 0; i < 16; i++) { colS[i] = 0.f; colP[i] = 0.f; colC[i] = 0.f; }

        #pragma unroll
        for (int nj = 0; nj < 8; nj++) {
            const int nb = warp_n * 64 + nj * 8 + cq * 2;
            const int l0 = labT[nb];
            const int l1 = labT[nb + 1];
            #pragma unroll
            for (int mi = 0; mi < 2; mi++) {
                #pragma unroll
                for (int s = 0; s < 2; s++) {
                    const int i4 = mi * 2 + s;
                    float v0 = c[mi][nj][s * 2 + 0];
                    float v1 = c[mi][nj][s * 2 + 1];
                    float e0 = __expf(v0);
                    float e1 = __expf(v1);
                    accS[i4] += e0;           colS[nj * 2]     += e0;
                    accS[i4] += e1;           colS[nj * 2 + 1] += e1;
                    if (labI[i4] == l0) {
                        accP[i4] += v0; accC[i4] += 1.f;
                        colP[nj * 2] += v0; colC[nj * 2] += 1.f;
                    }
                    if (labI[i4] == l1) {
                        accP[i4] += v1; accC[i4] += 1.f;
                        colP[nj * 2 + 1] += v1; colC[nj * 2 + 1] += 1.f;
                    }
                }
            }
        }

        // Reduce column partials across rq (lanes sharing cq), atomics by rq==0.
        #pragma unroll
        for (int i = 0; i < 16; i++) {
            colS[i] += __shfl_xor_sync(0xFFFFFFFFu, colS[i], 4);
            colS[i] += __shfl_xor_sync(0xFFFFFFFFu, colS[i], 8);
            colS[i] += __shfl_xor_sync(0xFFFFFFFFu, colS[i], 16);
            colP[i] += __shfl_xor_sync(0xFFFFFFFFu, colP[i], 4);
            colP[i] += __shfl_xor_sync(0xFFFFFFFFu, colP[i], 8);
            colP[i] += __shfl_xor_sync(0xFFFFFFFFu, colP[i], 16);
            colC[i] += __shfl_xor_sync(0xFFFFFFFFu, colC[i], 4);
            colC[i] += __shfl_xor_sync(0xFFFFFFFFu, colC[i], 8);
            colC[i] += __shfl_xor_sync(0xFFFFFFFFu, colC[i], 16);
        }
        if (lane < 4) {
            #pragma unroll
            for (int nj = 0; nj < 8; nj++) {
                #pragma unroll
                for (int e = 0; e < 2; e++) {
                    int ci  = nj * 2 + e;
                    int col = col0 + warp_n * 64 + nj * 8 + lane * 2 + e;
                    atomicAdd(&g_S[col], colS[ci]);
                    atomicAdd(&g_P[col], colP[ci]);
                    atomicAdd(&g_C[col], colC[ci]);
                }
            }
        }
    }

    // Row reduction across cq (quad), atomics by cq==0.
    #pragma unroll
    for (int i = 0; i < 4; i++) {
        accS[i] += __shfl_xor_sync(0xFFFFFFFFu, accS[i], 1);
        accS[i] += __shfl_xor_sync(0xFFFFFFFFu, accS[i], 2);
        accP[i] += __shfl_xor_sync(0xFFFFFFFFu, accP[i], 1);
        accP[i] += __shfl_xor_sync(0xFFFFFFFFu, accP[i], 2);
        accC[i] += __shfl_xor_sync(0xFFFFFFFFu, accC[i], 1);
        accC[i] += __shfl_xor_sync(0xFFFFFFFFu, accC[i], 2);
    }
    if (cq == 0) {
        #pragma unroll
        for (int i = 0; i < 4; i++) {
            atomicAdd(&g_S[gRow[i]], accS[i]);
            atomicAdd(&g_P[gRow[i]], accP[i]);
            atomicAdd(&g_C[gRow[i]], accC[i]);
        }
    }
}

// ---------------------------------------------------------------------------
// Kernel 3a/3b: finalize.
// ---------------------------------------------------------------------------
__global__ void finalize_partial_kernel() {
    int i = blockIdx.x * 256 + threadIdx.x;
    float c = g_C[i];
    float term = g_P[i] / fmaxf(c, 1.0f) - __logf(g_S[i] + 1e-6f);
    #pragma unroll
    for (int o = 16; o > 0; o >>= 1) term += __shfl_xor_sync(0xFFFFFFFFu, term, o);
    __shared__ float ws[8];
    if ((threadIdx.x & 31) == 0) ws[threadIdx.x >> 5] = term;
    __syncthreads();
    if (threadIdx.x == 0) {
        float s = 0.f;
        #pragma unroll
        for (int w = 0; w < 8; w++) s += ws[w];
        atomicAdd(&g_sum, s);
    }
}

__global__ void finalize_write_kernel(float* __restrict__ out) {
    out[0] = -g_sum / (float)NROW;
}

// ---------------------------------------------------------------------------
extern "C" void kernel_launch(void* const* d_in, const int* in_sizes, int n_in,
                              void* d_out, int out_size) {
    const float* feats = (const float*)d_in[0];
    const void*  labs  = d_in[1];
    float*       out   = (float*)d_out;

    cudaFuncSetAttribute(supcon_sym_kernel,
                         cudaFuncAttributeMaxDynamicSharedMemorySize, SM_TOTAL);

    detect_labdtype_kernel<<<1, 256>>>((const unsigned*)labs);
    prep_kernel<<<NROW / 8, 256>>>(feats, labs);

    supcon_sym_kernel<<<NPAIRS, NTHREADS, SM_TOTAL>>>();

    finalize_partial_kernel<<<NROW / 256, 256>>>();
    finalize_write_kernel<<<1, 1>>>(out);
}